// round 1
// baseline (speedup 1.0000x reference)
#include <cuda_runtime.h>
#include <cuda_bf16.h>
#include <cstdint>

// DiagLinear: y[m, o*P + p] = sum_i x[m, p*DIN + i] * W[p, o, i] + bias[o*P + p]
// P=16, DIN=256, DOUT=256, M = 8*2048 = 16384.
//
// Round 1 baseline: register-blocked tiled SGEMM on CUDA cores.
// TM=128 x TN=64 x TK=32 tiles, 256 threads, 8x4 micro-tile per thread.

#define P_PART 16
#define DIN    256
#define DOUT   256
#define TM     128
#define TN     64
#define TK     32

__global__ __launch_bounds__(256, 4)
void diag_linear_kernel(const float* __restrict__ x,
                        const float* __restrict__ w,
                        const float* __restrict__ bias,
                        float* __restrict__ y,
                        int M)
{
    // Grid: x = partition p (16), y = n-chunk (DOUT/TN = 4), z = m-tile (M/TM)
    const int p  = blockIdx.x;
    const int n0 = blockIdx.y * TN;
    const int m0 = blockIdx.z * TM;

    __shared__ float Xs[TM][TK + 1];   // +1 pad: conflict-free scalar stores / reads
    __shared__ float Ws[TK][TN + 1];   // transposed W chunk, +1 pad

    const int tid = threadIdx.x;       // 0..255
    const int tx  = tid & 15;          // 16 col-groups (4 cols each)
    const int ty  = tid >> 4;          // 16 row-groups (8 rows each)

    float acc[8][4];
#pragma unroll
    for (int r = 0; r < 8; r++)
#pragma unroll
        for (int c = 0; c < 4; c++)
            acc[r][c] = 0.0f;

    const int ld_row_x = tid >> 3;           // 0..31 base row for X loads (idx>>3 with offsets)
    const float* xbase = x + (size_t)m0 * (P_PART * DIN) + (size_t)p * DIN;
    const float* wbase = w + ((size_t)p * DOUT + n0) * DIN;
    (void)ld_row_x;

    for (int k0 = 0; k0 < DIN; k0 += TK) {
        // ---- Load X tile: TM x TK floats (128x32), float4 vectorized, coalesced ----
#pragma unroll
        for (int i = 0; i < 4; i++) {
            int idx = tid + i * 256;          // 0..1023
            int row = idx >> 3;               // 0..127
            int kv  = (idx & 7) << 2;         // 0,4,...,28
            float4 v = *reinterpret_cast<const float4*>(
                xbase + (size_t)row * (P_PART * DIN) + (k0 + kv));
            Xs[row][kv + 0] = v.x;
            Xs[row][kv + 1] = v.y;
            Xs[row][kv + 2] = v.z;
            Xs[row][kv + 3] = v.w;
        }
        // ---- Load W tile: TN x TK floats (64x32), transposed into Ws[kk][col] ----
#pragma unroll
        for (int i = 0; i < 2; i++) {
            int idx = tid + i * 256;          // 0..511
            int col = idx >> 3;               // 0..63
            int kv  = (idx & 7) << 2;         // 0,4,...,28
            float4 v = *reinterpret_cast<const float4*>(
                wbase + (size_t)col * DIN + (k0 + kv));
            Ws[kv + 0][col] = v.x;
            Ws[kv + 1][col] = v.y;
            Ws[kv + 2][col] = v.z;
            Ws[kv + 3][col] = v.w;
        }
        __syncthreads();

        // ---- Compute: 8x4 micro-tile per thread over TK ----
#pragma unroll 8
        for (int kk = 0; kk < TK; kk++) {
            float a[8], b[4];
#pragma unroll
            for (int r = 0; r < 8; r++) a[r] = Xs[ty * 8 + r][kk];
#pragma unroll
            for (int c = 0; c < 4; c++) b[c] = Ws[kk][tx * 4 + c];
#pragma unroll
            for (int r = 0; r < 8; r++)
#pragma unroll
                for (int c = 0; c < 4; c++)
                    acc[r][c] = fmaf(a[r], b[c], acc[r][c]);
        }
        __syncthreads();
    }

    // ---- Epilogue: y[m, o*P + p] = acc + bias[o*P + p] ----
    // Strided 64B-apart 4B stores; partition-partner blocks are consecutive bids
    // (grid.x = p) so interleaved lines assemble in L2 before eviction.
#pragma unroll
    for (int r = 0; r < 8; r++) {
        int m = m0 + ty * 8 + r;
        float* yrow = y + (size_t)m * (DOUT * P_PART);
#pragma unroll
        for (int c = 0; c < 4; c++) {
            int o = n0 + tx * 4 + c;
            yrow[o * P_PART + p] = acc[r][c] + bias[o * P_PART + p];
        }
    }
}

extern "C" void kernel_launch(void* const* d_in, const int* in_sizes, int n_in,
                              void* d_out, int out_size)
{
    const float* x    = (const float*)d_in[0];   // (8, 2048, 4096) fp32
    const float* w    = (const float*)d_in[1];   // (16, 256, 256) fp32
    const float* bias = (const float*)d_in[2];   // (4096,) fp32
    float* y = (float*)d_out;

    int M = in_sizes[0] / (P_PART * DIN);        // 16384

    dim3 grid(P_PART, DOUT / TN, M / TM);        // (16, 4, 128)
    dim3 block(256);
    diag_linear_kernel<<<grid, block>>>(x, w, bias, y, M);
}

// round 6
// speedup vs baseline: 2.0729x; 2.0729x over previous
#include <cuda_runtime.h>
#include <cstdint>

// DiagLinear: y[m, n*16+p] = sum_k x[m, p*256+k] * w[p, n, k] + bias[n*16+p]
// P=16, DIN=DOUT=256, M=16384.
//
// Kernel 1 (diag_gemm): per-partition TF32 GEMM via mma.sync.m16n8k8 (legacy
//   HMMA path; tcgen05 unavailable at .target sm_103). CTA 512thr, tile
//   M=128 x N=256, KC=32 x 8 chunks, triple-buffered smem, cvt.rna rounding.
//   Stores CONTIGUOUS to scratch ytmp[p][m][n] (avoids 8x sector-amplified
//   interleaved stores).
// Kernel 2 (transpose_bias): coalesced smem transpose ytmp -> y + bias.

#define P_PART 16
#define DIN    256
#define DOUT   256
#define MROWS  16384
#define KC     32
#define NCHUNK 8

#define ABUF_BYTES 16384            // 128 rows x 128B
#define BBUF_BYTES 32768            // 256 rows x 128B
#define SMEM_B_OFF (3 * ABUF_BYTES) // 49152
#define GEMM_SMEM  (3 * ABUF_BYTES + 3 * BBUF_BYTES)  // 147456

#define TPAD 260                    // 256 + 4 floats pad
#define TR_SMEM (4 * 16 * TPAD * 4) // 66560

__device__ float g_ytmp[(size_t)MROWS * P_PART * DOUT];   // [p][m][n], 256MB

static __device__ __forceinline__ uint32_t smem_u32(const void* p) {
    uint32_t a;
    asm("{ .reg .u64 t; cvta.to.shared.u64 t, %1; cvt.u32.u64 %0, t; }" : "=r"(a) : "l"(p));
    return a;
}

static __device__ __forceinline__ uint32_t f2tf32(float v) {
    uint32_t u;
    asm("cvt.rna.tf32.f32 %0, %1;" : "=r"(u) : "f"(v));
    return u;
}

__global__ __launch_bounds__(512, 1)
void diag_gemm(const float* __restrict__ x, const float* __restrict__ w)
{
    extern __shared__ char smem[];
    const int tid  = threadIdx.x;
    const int wid  = tid >> 5;
    const int lane = tid & 31;
    const int p    = blockIdx.x;            // fastest (write locality irrelevant now)
    const int m0   = blockIdx.y * 128;

    const int warp_m = wid >> 2;            // 0..3 -> 32 rows
    const int warp_n = wid & 3;             // 0..3 -> 64 cols

    const float* xbase = x + (size_t)m0 * (P_PART * DIN) + (size_t)p * DIN;
    const float* wbase = w + (size_t)p * (DOUT * DIN);

    // ---- per-lane ldmatrix address precompute ----
    const int g  = lane >> 3;
    const int l8 = lane & 7;
    // A frag (m16k8): matrices a0..a3 = (r0-7,k0-3),(r8-15,k0-3),(r0-7,k4-7),(r8-15,k4-7)
    const int rowA = warp_m * 32 + (g & 1) * 8 + l8;
    const int cA   = g >> 1;
    // B frag (k8n8, B stored [n][k]): matrices = (n0-7,k0-3),(n0-7,k4-7),(n8-15,k0-3),(n8-15,k4-7)
    const int rowB = warp_n * 64 + (g >> 1) * 8 + l8;
    const int cB   = g & 1;

    const uint32_t sbase  = smem_u32(smem);
    const uint32_t aAddr0 = sbase + rowA * 128;
    const uint32_t bAddr0 = sbase + SMEM_B_OFF + rowB * 128;
    const int swA = rowA & 7, swB = rowB & 7;

    float acc[2][8][4];
#pragma unroll
    for (int mm = 0; mm < 2; mm++)
#pragma unroll
        for (int nn = 0; nn < 8; nn++)
#pragma unroll
            for (int c = 0; c < 4; c++) acc[mm][nn][c] = 0.0f;

    float4 ra[2], rb[4];

#define LDG_A(KCI)                                                              \
    _Pragma("unroll")                                                           \
    for (int i = 0; i < 2; i++) {                                               \
        int idx = i * 512 + tid;                                                \
        ra[i] = *reinterpret_cast<const float4*>(                               \
            xbase + (size_t)(idx >> 3) * (P_PART * DIN) + (KCI) * KC + (idx & 7) * 4); \
    }

#define LDG_B(KCI)                                                              \
    _Pragma("unroll")                                                           \
    for (int i = 0; i < 4; i++) {                                               \
        int idx = i * 512 + tid;                                                \
        rb[i] = *reinterpret_cast<const float4*>(                               \
            wbase + (size_t)(idx >> 3) * DIN + (KCI) * KC + (idx & 7) * 4);     \
    }

#define STS_AB(BUF)                                                             \
    _Pragma("unroll")                                                           \
    for (int i = 0; i < 2; i++) {                                               \
        int idx = i * 512 + tid;                                                \
        int row = idx >> 3, q = idx & 7;                                        \
        uint4 u = make_uint4(f2tf32(ra[i].x), f2tf32(ra[i].y),                  \
                             f2tf32(ra[i].z), f2tf32(ra[i].w));                 \
        *reinterpret_cast<uint4*>(smem + (BUF) * ABUF_BYTES + row * 128 +       \
                                  ((q ^ (row & 7)) << 4)) = u;                  \
    }                                                                           \
    _Pragma("unroll")                                                           \
    for (int i = 0; i < 4; i++) {                                               \
        int idx = i * 512 + tid;                                                \
        int row = idx >> 3, q = idx & 7;                                        \
        uint4 u = make_uint4(f2tf32(rb[i].x), f2tf32(rb[i].y),                  \
                             f2tf32(rb[i].z), f2tf32(rb[i].w));                 \
        *reinterpret_cast<uint4*>(smem + SMEM_B_OFF + (BUF) * BBUF_BYTES +      \
                                  row * 128 + ((q ^ (row & 7)) << 4)) = u;      \
    }

#define COMPUTE(BUF)                                                            \
    {                                                                           \
        const uint32_t abase = aAddr0 + (BUF) * ABUF_BYTES;                     \
        const uint32_t bbase = bAddr0 + (BUF) * BBUF_BYTES;                     \
        _Pragma("unroll")                                                       \
        for (int ks = 0; ks < 4; ks++) {                                        \
            const int cb = ks * 2;                                              \
            uint32_t a[2][4], b[4][4];                                          \
            _Pragma("unroll")                                                   \
            for (int mm = 0; mm < 2; mm++) {                                    \
                uint32_t ad = abase + mm * 2048 + (((cb + cA) ^ swA) << 4);     \
                asm volatile(                                                   \
                    "ldmatrix.sync.aligned.m8n8.x4.shared.b16 {%0,%1,%2,%3}, [%4];" \
                    : "=r"(a[mm][0]), "=r"(a[mm][1]), "=r"(a[mm][2]), "=r"(a[mm][3]) \
                    : "r"(ad));                                                 \
            }                                                                   \
            _Pragma("unroll")                                                   \
            for (int q = 0; q < 4; q++) {                                       \
                uint32_t bd = bbase + q * 2048 + (((cb + cB) ^ swB) << 4);      \
                asm volatile(                                                   \
                    "ldmatrix.sync.aligned.m8n8.x4.shared.b16 {%0,%1,%2,%3}, [%4];" \
                    : "=r"(b[q][0]), "=r"(b[q][1]), "=r"(b[q][2]), "=r"(b[q][3]) \
                    : "r"(bd));                                                 \
            }                                                                   \
            _Pragma("unroll")                                                   \
            for (int mm = 0; mm < 2; mm++)                                      \
                _Pragma("unroll")                                               \
                for (int nn = 0; nn < 8; nn++) {                                \
                    asm volatile(                                               \
                        "mma.sync.aligned.m16n8k8.row.col.f32.tf32.tf32.f32 "   \
                        "{%0,%1,%2,%3}, {%4,%5,%6,%7}, {%8,%9}, {%0,%1,%2,%3};" \
                        : "+f"(acc[mm][nn][0]), "+f"(acc[mm][nn][1]),           \
                          "+f"(acc[mm][nn][2]), "+f"(acc[mm][nn][3])            \
                        : "r"(a[mm][0]), "r"(a[mm][1]), "r"(a[mm][2]), "r"(a[mm][3]), \
                          "r"(b[nn >> 1][(nn & 1) * 2]), "r"(b[nn >> 1][(nn & 1) * 2 + 1])); \
                }                                                               \
        }                                                                       \
    }

    // ---- prologue ----
    LDG_A(0); LDG_B(0);
    STS_AB(0);
    LDG_A(1); LDG_B(1);
    __syncthreads();

    // ---- main loop: 1 sync/iter, triple buffer, prefetch distance 2 ----
#pragma unroll 1
    for (int kc = 0; kc < NCHUNK; kc++) {
        const int nb = (kc + 1) % 3;
        if (kc + 1 < NCHUNK) { STS_AB(nb); }           // chunk kc+1 (regs) -> buf
        if (kc + 2 < NCHUNK) { LDG_A(kc + 2); LDG_B(kc + 2); }
        COMPUTE(kc % 3);
        __syncthreads();
    }

    // ---- epilogue: contiguous store to ytmp[p][m][n] ----
    {
        float* yt = g_ytmp + ((size_t)p * MROWS + m0) * DOUT;
        const int r0 = lane >> 2;
        const int c0 = (lane & 3) * 2;
#pragma unroll
        for (int mm = 0; mm < 2; mm++) {
            const int mr = warp_m * 32 + mm * 16 + r0;
#pragma unroll
            for (int nn = 0; nn < 8; nn++) {
                const int n = warp_n * 64 + nn * 8 + c0;
                *reinterpret_cast<float2*>(yt + (size_t)mr * DOUT + n) =
                    make_float2(acc[mm][nn][0], acc[mm][nn][1]);
                *reinterpret_cast<float2*>(yt + (size_t)(mr + 8) * DOUT + n) =
                    make_float2(acc[mm][nn][2], acc[mm][nn][3]);
            }
        }
    }
}

// ---- Kernel 2: transpose [p][m][n] -> y[m][n*16+p] + bias, fully coalesced ----
__global__ __launch_bounds__(256)
void transpose_bias(const float* __restrict__ bias, float* __restrict__ y)
{
    extern __shared__ float ts[];     // [4 m][16 p][TPAD]
    const int tid = threadIdx.x;
    const int mb  = blockIdx.x * 4;

    // load 4 m-rows x 16 p x 256 n (coalesced 1KB rows)
#pragma unroll
    for (int i = 0; i < 16; i++) {
        int lin = i * 256 + tid;               // 0..4095 float4s
        int n4  = lin & 63;
        int pp  = (lin >> 6) & 15;
        int m   = lin >> 10;
        float4 v = *reinterpret_cast<const float4*>(
            g_ytmp + ((size_t)pp * MROWS + mb + m) * DOUT + n4 * 4);
        *reinterpret_cast<float4*>(ts + (m * 16 + pp) * TPAD + n4 * 4) = v;
    }
    __syncthreads();

    // write y rows: 4 x 16KB contiguous
#pragma unroll
    for (int m = 0; m < 4; m++) {
        float* yrow = y + (size_t)(mb + m) * (DOUT * P_PART);
#pragma unroll
        for (int i = 0; i < 4; i++) {
            int o  = (i * 256 + tid) * 4;      // output offset, p-fastest
            int pb = o & 15;                   // 0,4,8,12
            int n  = o >> 4;
            float4 bv = *reinterpret_cast<const float4*>(bias + o);
            float4 r;
            r.x = ts[(m * 16 + pb + 0) * TPAD + n] + bv.x;
            r.y = ts[(m * 16 + pb + 1) * TPAD + n] + bv.y;
            r.z = ts[(m * 16 + pb + 2) * TPAD + n] + bv.z;
            r.w = ts[(m * 16 + pb + 3) * TPAD + n] + bv.w;
            *reinterpret_cast<float4*>(yrow + o) = r;
        }
    }
}

extern "C" void kernel_launch(void* const* d_in, const int* in_sizes, int n_in,
                              void* d_out, int out_size)
{
    const float* x    = (const float*)d_in[0];
    const float* w    = (const float*)d_in[1];
    const float* bias = (const float*)d_in[2];
    float* y = (float*)d_out;

    int M = in_sizes[0] / (P_PART * DIN);      // 16384

    cudaFuncSetAttribute(diag_gemm,
                         cudaFuncAttributeMaxDynamicSharedMemorySize, GEMM_SMEM);
    cudaFuncSetAttribute(transpose_bias,
                         cudaFuncAttributeMaxDynamicSharedMemorySize, TR_SMEM);

    diag_gemm<<<dim3(P_PART, M / 128), 512, GEMM_SMEM>>>(x, w);
    transpose_bias<<<M / 4, 256, TR_SMEM>>>(bias, y);
}